// round 16
// baseline (speedup 1.0000x reference)
#include <cuda_runtime.h>
#include <cuda_fp16.h>
#include <cstdint>

#define N_NODES 50000
#define DS 127
#define DPAD 128
#define NE 800000
#define EPSF 1e-7f
#define GR 64        // rows per tile
#define TILES 2      // tiles per block
#define HSTRIDE 136  // smem stride in halves (conflict-free ldmatrix)

__device__ __align__(16) __half g_x16[N_NODES * DPAD];
__device__ __align__(16) __half g_h16[N_NODES * DPAD];
__device__ __align__(16) __half g_z[N_NODES * DPAD];
__device__ __align__(16) __half g_agg[N_NODES * DPAD];
__device__ __align__(16) __half g_Wt[2 * DPAD * DPAD];

__device__ __forceinline__ float warp_sum(float v) {
#pragma unroll
    for (int o = 16; o; o >>= 1) v += __shfl_xor_sync(0xffffffffu, v, o);
    return v;
}

__device__ __forceinline__ void ldsm4(uint32_t* r, uint32_t addr) {
    asm volatile("ldmatrix.sync.aligned.m8n8.x4.shared.b16 {%0,%1,%2,%3}, [%4];"
                 : "=r"(r[0]), "=r"(r[1]), "=r"(r[2]), "=r"(r[3]) : "r"(addr));
}

__device__ __forceinline__ void mma16816(float* c, const uint32_t* a,
                                         uint32_t b0, uint32_t b1) {
    asm volatile(
        "mma.sync.aligned.m16n8k16.row.col.f32.f16.f16.f32 "
        "{%0,%1,%2,%3}, {%4,%5,%6,%7}, {%8,%9}, {%0,%1,%2,%3};"
        : "+f"(c[0]), "+f"(c[1]), "+f"(c[2]), "+f"(c[3])
        : "r"(a[0]), "r"(a[1]), "r"(a[2]), "r"(a[3]), "r"(b0), "r"(b1));
}

__device__ __forceinline__ void cp16(uint32_t smem_addr, const void* gptr) {
    asm volatile("cp.async.cg.shared.global [%0], [%1], 16;"
                 :: "r"(smem_addr), "l"(gptr));
}

__device__ __forceinline__ void pdl_trigger() {
    asm volatile("griddepcontrol.launch_dependents;");
}
__device__ __forceinline__ void pdl_wait() {
    asm volatile("griddepcontrol.wait;" ::: "memory");
}

// Merged prep: W1,W2 -> g_Wt (fp16 n-major, zero pads), x -> g_x16 (fp16 padded)
__global__ void k_prep(const float* __restrict__ W1, const float* __restrict__ W2,
                       const float* __restrict__ x) {
    pdl_trigger();
    int idx = blockIdx.x * 256 + threadIdx.x;
    const int WTOT = 2 * DPAD * DPAD;
    if (idx < WTOT) {
        int l = idx >> 14, rem = idx & 16383, n = rem >> 7, k = rem & 127;
        const float* W = l ? W2 : W1;
        float v = (k < DS && n < DS) ? W[k * DS + n] : 0.f;
        g_Wt[idx] = __float2half(v);
    }
    int xi = idx - WTOT;
    if (xi >= 0 && xi < N_NODES * DPAD) {
        int row = xi >> 7, c = xi & 127;
        g_x16[xi] = __float2half((c < DS) ? x[row * DS + c] : 0.f);
    }
}

// Fill one 64-row h tile. layer==0: cp.async copy from g_x16 (caller commits/waits).
// layer==1: h = relu(agg)+x16, stored to smem AND g_h16.
__device__ __forceinline__ void build_h(__half* Ht, uint32_t ht_base,
                                        int row0, int layer, int tid) {
    if (layer == 0) {
        for (int j = tid; j < GR * 16; j += 256) {
            int r = j >> 4, ch = j & 15;
            int row = row0 + r;
            if (row < N_NODES) {
                cp16(ht_base + (uint32_t)(r * HSTRIDE + ch * 8) * 2,
                     (const uint4*)(g_x16 + (size_t)row * DPAD) + ch);
            } else {
                *(uint4*)(Ht + r * HSTRIDE + ch * 8) = make_uint4(0u, 0u, 0u, 0u);
            }
        }
    } else {
        for (int j = tid; j < GR * 16; j += 256) {
            int r = j >> 4, ch = j & 15;
            int row = row0 + r;
            uint4 v = make_uint4(0u, 0u, 0u, 0u);
            if (row < N_NODES) {
                v = ((const uint4*)(g_x16 + (size_t)row * DPAD))[ch];
                uint4 a = ((const uint4*)(g_agg + (size_t)row * DPAD))[ch];
                __half2* vh = (__half2*)&v;
                __half2* ah = (__half2*)&a;
#pragma unroll
                for (int i = 0; i < 4; i++) {
                    float2 xf = __half22float2(vh[i]);
                    float2 af = __half22float2(ah[i]);
                    vh[i] = __floats2half2_rn(xf.x + fmaxf(af.x, 0.f),
                                              xf.y + fmaxf(af.y, 0.f));
                }
                ((uint4*)(g_h16 + (size_t)row * DPAD))[ch] = v;
            }
            *(uint4*)(Ht + r * HSTRIDE + ch * 8) = v;
        }
    }
}

// One 64-row tile: mma from Ht + epilogue (z store, agg zero).
__device__ __forceinline__ void mma_tile(uint32_t ht_base, uint32_t wt_s,
                                         const float* b_s, int row0, int tid) {
    int lane = tid & 31, wid = tid >> 5;
    int wm = wid >> 2, wn = wid & 3;

    uint32_t aaddr[2];
#pragma unroll
    for (int mt = 0; mt < 2; mt++) {
        int rowA = wm * 32 + mt * 16 + (lane & 15);
        int kA   = (lane >> 4) * 8;
        aaddr[mt] = ht_base + (uint32_t)(rowA * HSTRIDE + kA) * 2;
    }
    uint32_t baddr[2];
#pragma unroll
    for (int p = 0; p < 2; p++) {
        int rowB = wn * 32 + p * 16 + (lane >> 4) * 8 + (lane & 7);
        int kB   = ((lane >> 3) & 1) * 8;
        baddr[p] = wt_s + (uint32_t)(rowB * HSTRIDE + kB) * 2;
    }

    float c[2][4][4];
#pragma unroll
    for (int mt = 0; mt < 2; mt++)
#pragma unroll
        for (int nt = 0; nt < 4; nt++)
#pragma unroll
            for (int j = 0; j < 4; j++) c[mt][nt][j] = 0.f;

#pragma unroll
    for (int ks = 0; ks < 8; ks++) {
        uint32_t kb = (uint32_t)(ks * 16 * 2);
        uint32_t a[2][4], bq[2][4];
        ldsm4(a[0], aaddr[0] + kb);
        ldsm4(a[1], aaddr[1] + kb);
        ldsm4(bq[0], baddr[0] + kb);
        ldsm4(bq[1], baddr[1] + kb);
#pragma unroll
        for (int mt = 0; mt < 2; mt++)
#pragma unroll
            for (int nt = 0; nt < 4; nt++)
                mma16816(c[mt][nt], a[mt], bq[nt >> 1][(nt & 1) * 2],
                         bq[nt >> 1][(nt & 1) * 2 + 1]);
    }

    int r_in = lane >> 2, col_in = 2 * (lane & 3);
#pragma unroll
    for (int mt = 0; mt < 2; mt++) {
#pragma unroll
        for (int nt = 0; nt < 4; nt++) {
            int row = row0 + wm * 32 + mt * 16 + r_in;
            int col = wn * 32 + nt * 8 + col_in;
            float bb0 = b_s[col], bb1 = b_s[col + 1];
            if (row < N_NODES)
                *(__half2*)(g_z + (size_t)row * DPAD + col) =
                    __floats2half2_rn(c[mt][nt][0] + bb0, c[mt][nt][1] + bb1);
            if (row + 8 < N_NODES)
                *(__half2*)(g_z + (size_t)(row + 8) * DPAD + col) =
                    __floats2half2_rn(c[mt][nt][2] + bb0, c[mt][nt][3] + bb1);
        }
    }
    {
        uint4 zz = make_uint4(0u, 0u, 0u, 0u);
        uint4* a4 = (uint4*)(g_agg + (size_t)row0 * DPAD);
        for (int j = tid; j < GR * 16; j += 256) {
            int row = row0 + (j >> 4);
            if (row < N_NODES) a4[j] = zz;
        }
    }
}

// 128 rows per block as 2 x 64-row tiles; W loaded once; h double-buffered.
// PDL: layer 1 preloads W (prep output, transitively complete) before the wait
// on edge-1; layer 0 waits first (predecessor prep produces W/x16).
__global__ void __launch_bounds__(256, 3)
k_gemm(const float* __restrict__ b, int layer) {
    extern __shared__ __align__(16) char smem_raw[];
    __half* Wt  = (__half*)smem_raw;                   // [128][136]
    __half* Ht0 = Wt + DPAD * HSTRIDE;                 // [64][136]
    __half* Ht1 = Ht0 + GR * HSTRIDE;                  // [64][136]
    float*  b_s = (float*)(Ht1 + GR * HSTRIDE);        // [128]
    int tid  = threadIdx.x;
    int row0 = blockIdx.x * (GR * TILES);

    pdl_trigger();

    uint32_t wt_s  = (uint32_t)__cvta_generic_to_shared(Wt);
    uint32_t ht0_s = (uint32_t)__cvta_generic_to_shared(Ht0);
    uint32_t ht1_s = (uint32_t)__cvta_generic_to_shared(Ht1);

    if (tid < DPAD) b_s[tid] = (tid < DS) ? b[tid] : 0.f;   // input arg: independent

    if (layer) {
        // W from g_Wt (written by k_prep, >=2 kernels back) — safe pre-wait
        const uint4* src = (const uint4*)(g_Wt + DPAD * DPAD);
        for (int j = tid; j < 2048; j += 256) {
            int n = j >> 4, kc = j & 15;
            cp16(wt_s + (uint32_t)(n * HSTRIDE + kc * 8) * 2, src + j);
        }
    }

    pdl_wait();   // predecessor complete (prep for layer0; edge1 for layer1)

    if (!layer) {
        const uint4* src = (const uint4*)g_Wt;
        for (int j = tid; j < 2048; j += 256) {
            int n = j >> 4, kc = j & 15;
            cp16(wt_s + (uint32_t)(n * HSTRIDE + kc * 8) * 2, src + j);
        }
    }

    build_h(Ht0, ht0_s, row0, layer, tid);
    asm volatile("cp.async.commit_group;");
    asm volatile("cp.async.wait_group 0;");
    __syncthreads();

    build_h(Ht1, ht1_s, row0 + GR, layer, tid);
    asm volatile("cp.async.commit_group;");

    mma_tile(ht0_s, wt_s, b_s, row0, tid);

    asm volatile("cp.async.wait_group 0;");
    __syncthreads();

    mma_tile(ht1_s, wt_s, b_s, row0 + GR, tid);
}

// Warp processes 8 edges; metadata loads pre-wait (input args), gather/RED post.
__global__ void k_edge(const int* __restrict__ src, const int* __restrict__ dst,
                       const float* __restrict__ wt) {
    pdl_trigger();
    int warp = (blockIdx.x * blockDim.x + threadIdx.x) >> 5;
    int lane = threadIdx.x & 31;
    int e0 = warp * 8;

    int s = 0, d = 0;
    float w = 0.f;
    if (lane < 8) {
        s = src[e0 + lane];
        d = dst[e0 + lane];
        w = wt[e0 + lane];
    }

    pdl_wait();   // z / zeroed agg ready

    const uint2* z2 = (const uint2*)g_z;
    uint2 v[8];
#pragma unroll
    for (int i = 0; i < 8; i++) {
        int si = __shfl_sync(0xffffffffu, s, i);
        v[i] = z2[(size_t)si * 32 + lane];
    }
#pragma unroll
    for (int i = 0; i < 8; i++) {
        int   di = __shfl_sync(0xffffffffu, d, i);
        float wi = __shfl_sync(0xffffffffu, w, i);
        float2 f0 = __half22float2(*(const __half2*)&v[i].x);
        float2 f1 = __half22float2(*(const __half2*)&v[i].y);
        __half2 m0 = __floats2half2_rn(f0.x * wi, f0.y * wi);
        __half2 m1 = __floats2half2_rn(f1.x * wi, f1.y * wi);
        __half* a = g_agg + (size_t)di * DPAD + 4 * lane;
        asm volatile("red.global.add.noftz.v2.f16x2 [%0], {%1,%2};"
                     :: "l"(a), "r"(*(unsigned*)&m0), "r"(*(unsigned*)&m1)
                     : "memory");
    }
}

// h2 = relu(agg2) + h1;  out = expmap0(h2). h16 (gemm2 output, 2 back) pre-wait.
__global__ void k_final(float* __restrict__ out) {
    pdl_trigger();
    int warp = (blockIdx.x * blockDim.x + threadIdx.x) >> 5;
    int lane = threadIdx.x & 31;
    if (warp >= N_NODES) { pdl_wait(); return; }
    float hv[4];
#pragma unroll
    for (int j = 0; j < 4; j++) {
        int c = lane + 32 * j;
        hv[j] = __half2float(g_h16[warp * DPAD + c]);
    }

    pdl_wait();   // agg2 ready

    float v[4];
    float n2 = 0.f;
#pragma unroll
    for (int j = 0; j < 4; j++) {
        int c = lane + 32 * j;
        float a = __half2float(g_agg[warp * DPAD + c]);
        v[j] = (c < DS) ? (fmaxf(a, 0.f) + hv[j]) : 0.f;
        n2 += v[j] * v[j];
    }
    n2 = warp_sum(n2);
    float n = fmaxf(sqrtf(n2), EPSF);
    float t = coshf(n);
    float f = sinhf(n) / n;
    if (lane == 0) out[warp * DPAD] = t;
#pragma unroll
    for (int j = 0; j < 4; j++) {
        int c = lane + 32 * j;
        if (c < DS) out[warp * DPAD + 1 + c] = f * v[j];
    }
}

static void launch_pdl(const void* fn, dim3 grid, dim3 block, size_t smem,
                       void** args) {
    cudaLaunchConfig_t cfg = {};
    cfg.gridDim = grid;
    cfg.blockDim = block;
    cfg.dynamicSmemBytes = smem;
    cfg.stream = 0;   // legacy default stream (same as <<<>>>)
    cudaLaunchAttribute at[1];
    at[0].id = cudaLaunchAttributeProgrammaticStreamSerialization;
    at[0].val.programmaticStreamSerializationAllowed = 1;
    cfg.attrs = at;
    cfg.numAttrs = 1;
    cudaLaunchKernelExC(&cfg, fn, args);
}

extern "C" void kernel_launch(void* const* d_in, const int* in_sizes, int n_in,
                              void* d_out, int out_size) {
    const float* x  = (const float*)d_in[0];
    const float* W1 = (const float*)d_in[1];
    const float* b1 = (const float*)d_in[2];
    const float* W2 = (const float*)d_in[3];
    const float* b2 = (const float*)d_in[4];
    const int*   es = (const int*)d_in[5];
    const int*   ed = (const int*)d_in[6];
    const float* ew = (const float*)d_in[7];
    float* out = (float*)d_out;

    const int smem_bytes = (DPAD * HSTRIDE + 2 * GR * HSTRIDE) * 2 + DPAD * 4;  // 70144
    cudaFuncSetAttribute(k_gemm, cudaFuncAttributeMaxDynamicSharedMemorySize, smem_bytes);

    dim3 blk(256, 1, 1);
    dim3 g_gemm((N_NODES + GR * TILES - 1) / (GR * TILES), 1, 1);  // 391
    dim3 g_edge((NE / 8) / 8, 1, 1);                               // 12500
    dim3 g_row((N_NODES * 32 + 255) / 256, 1, 1);                  // 6250
    int prep_total = 2 * DPAD * DPAD + N_NODES * DPAD;

    k_prep<<<(prep_total + 255) / 256, 256>>>(W1, W2, x);

    {
        int layer0 = 0, layer1 = 1;
        void* a_g1[] = { (void*)&b1, (void*)&layer0 };
        void* a_g2[] = { (void*)&b2, (void*)&layer1 };
        void* a_e[]  = { (void*)&es, (void*)&ed, (void*)&ew };
        void* a_f[]  = { (void*)&out };

        launch_pdl((const void*)k_gemm, g_gemm, blk, smem_bytes, a_g1);
        launch_pdl((const void*)k_edge, g_edge, blk, 0, a_e);
        launch_pdl((const void*)k_gemm, g_gemm, blk, smem_bytes, a_g2);
        launch_pdl((const void*)k_edge, g_edge, blk, 0, a_e);
        launch_pdl((const void*)k_final, g_row, blk, 0, a_f);
    }
}